// round 15
// baseline (speedup 1.0000x reference)
#include <cuda_runtime.h>
#include <cuda_bf16.h>
#include <cstdint>
#include <cstddef>

#define Bsz 128
#define Ssz 1024
#define Dsz 256
#define Hsz 256
#define G3  768

// Scratch: gx (fp32) + bf16 hi/lo splits of X and W_ih
__device__ float g_gx[(size_t)Bsz * Ssz * G3];
__device__ __nv_bfloat16 g_xhi[(size_t)Bsz * Ssz * Dsz];
__device__ __nv_bfloat16 g_xlo[(size_t)Bsz * Ssz * Dsz];
__device__ __nv_bfloat16 g_whi[Dsz * G3];
__device__ __nv_bfloat16 g_wlo[Dsz * G3];

typedef unsigned long long ull;

// ===========================================================================
// Split kernels: fp32 -> bf16 (hi) + bf16 (residual lo)
// ===========================================================================
__device__ __forceinline__ void split8(const float* src, __nv_bfloat16* dhi,
                                       __nv_bfloat16* dlo, size_t i) {
    float4 v0 = *reinterpret_cast<const float4*>(src + i);
    float4 v1 = *reinterpret_cast<const float4*>(src + i + 4);
    float v[8] = {v0.x, v0.y, v0.z, v0.w, v1.x, v1.y, v1.z, v1.w};
    unsigned h[4], l[4];
#pragma unroll
    for (int e = 0; e < 4; e++) {
        __nv_bfloat16 h0 = __float2bfloat16(v[e * 2]);
        __nv_bfloat16 h1 = __float2bfloat16(v[e * 2 + 1]);
        __nv_bfloat16 l0 = __float2bfloat16(v[e * 2]     - __bfloat162float(h0));
        __nv_bfloat16 l1 = __float2bfloat16(v[e * 2 + 1] - __bfloat162float(h1));
        h[e] = (unsigned)*reinterpret_cast<unsigned short*>(&h0) |
               ((unsigned)*reinterpret_cast<unsigned short*>(&h1) << 16);
        l[e] = (unsigned)*reinterpret_cast<unsigned short*>(&l0) |
               ((unsigned)*reinterpret_cast<unsigned short*>(&l1) << 16);
    }
    *reinterpret_cast<uint4*>(dhi + i) = make_uint4(h[0], h[1], h[2], h[3]);
    *reinterpret_cast<uint4*>(dlo + i) = make_uint4(l[0], l[1], l[2], l[3]);
}

__global__ __launch_bounds__(256) void split_x_kernel(const float* __restrict__ X) {
    size_t i = ((size_t)blockIdx.x * 256 + threadIdx.x) * 8;
    split8(X, g_xhi, g_xlo, i);
}
__global__ __launch_bounds__(256) void split_w_kernel(const float* __restrict__ W) {
    size_t i = ((size_t)blockIdx.x * 256 + threadIdx.x) * 8;
    split8(W, g_whi, g_wlo, i);
}

// ===========================================================================
// Kernel A: gx = X @ W_ih + b_ih via mma.sync bf16 (R13, passing, ~510us)
// ===========================================================================
#define APAD 40
#define BPAD 136
#define AS_BUF (128 * APAD * 2)
#define BS_BUF (32 * BPAD * 2)
#define BS_BASE (2 * AS_BUF)
#define SMEM_GEMM (BS_BASE + 2 * BS_BUF)
#define EPAD 136

__global__ __launch_bounds__(256, 2) void gemm_gx_mma(const float* __restrict__ bias)
{
    extern __shared__ char smg[];
    const int tid  = threadIdx.x;
    const int lane = tid & 31;
    const int wid  = tid >> 5;
    const int brow = blockIdx.y * 128;
    const int bcol = blockIdx.x * 128;
    const int warp_m = (wid >> 2) * 64;
    const int warp_n = (wid & 3) * 32;

    float c[4][4][4];
#pragma unroll
    for (int tm = 0; tm < 4; tm++)
#pragma unroll
        for (int tn = 0; tn < 4; tn++)
#pragma unroll
            for (int r = 0; r < 4; r++) c[tm][tn][r] = 0.f;

    int arow[2], ak8[2], bkr[2], bn8[2];
#pragma unroll
    for (int ch = 0; ch < 2; ch++) {
        int id = tid + ch * 256;
        arow[ch] = id >> 2;
        ak8[ch]  = (id & 3) * 8;
        bkr[ch]  = id >> 4;
        bn8[ch]  = (id & 15) * 8;
    }

    uint32_t smB;
    asm("{ .reg .u64 t; cvta.to.shared.u64 t, %1; cvt.u32.u64 %0, t; }"
        : "=r"(smB) : "l"(smg));

    const uint32_t aLaneOff = (uint32_t)(((lane & 15) * APAD + (lane >> 4) * 8) * 2);
    const uint32_t bLaneOff = (uint32_t)(((((lane >> 3) & 1) * 8 + (lane & 7)) * BPAD
                                          + (lane >> 4) * 8) * 2);

    uint4 ra[2], rb[2];
#pragma unroll
    for (int ch = 0; ch < 2; ch++) {
        ra[ch] = *reinterpret_cast<const uint4*>(
            &g_xhi[(size_t)(brow + arow[ch]) * Dsz + ak8[ch]]);
        rb[ch] = *reinterpret_cast<const uint4*>(
            &g_whi[(size_t)bkr[ch] * G3 + bcol + bn8[ch]]);
    }

#pragma unroll 1
    for (int it = 0; it < 24; it++) {
        const int buf = it & 1;
        __nv_bfloat16* As = reinterpret_cast<__nv_bfloat16*>(smg + buf * AS_BUF);
        __nv_bfloat16* Bs = reinterpret_cast<__nv_bfloat16*>(smg + BS_BASE + buf * BS_BUF);

#pragma unroll
        for (int ch = 0; ch < 2; ch++) {
            *reinterpret_cast<uint4*>(&As[arow[ch] * APAD + ak8[ch]]) = ra[ch];
            *reinterpret_cast<uint4*>(&Bs[bkr[ch] * BPAD + bn8[ch]]) = rb[ch];
        }
        __syncthreads();

        if (it + 1 < 24) {
            int p  = (it + 1) >> 3;
            int k0 = ((it + 1) & 7) * 32;
            const __nv_bfloat16* Ag = (p < 2) ? g_xhi : g_xlo;
            const __nv_bfloat16* Bg = (p == 1) ? g_wlo : g_whi;
#pragma unroll
            for (int ch = 0; ch < 2; ch++) {
                ra[ch] = *reinterpret_cast<const uint4*>(
                    &Ag[(size_t)(brow + arow[ch]) * Dsz + k0 + ak8[ch]]);
                rb[ch] = *reinterpret_cast<const uint4*>(
                    &Bg[(size_t)(k0 + bkr[ch]) * G3 + bcol + bn8[ch]]);
            }
        }

        const uint32_t asb = smB + (uint32_t)(buf * AS_BUF);
        const uint32_t bsb = smB + (uint32_t)(BS_BASE + buf * BS_BUF);
#pragma unroll
        for (int kh = 0; kh < 2; kh++) {
            uint32_t a[4][4];
#pragma unroll
            for (int tm = 0; tm < 4; tm++) {
                uint32_t addr = asb + aLaneOff +
                    (uint32_t)(((warp_m + tm * 16) * APAD + kh * 16) * 2);
                asm volatile(
                    "ldmatrix.sync.aligned.m8n8.x4.shared.b16 {%0,%1,%2,%3}, [%4];"
                    : "=r"(a[tm][0]), "=r"(a[tm][1]), "=r"(a[tm][2]), "=r"(a[tm][3])
                    : "r"(addr));
            }
            uint32_t b[4][2];
#pragma unroll
            for (int tnh = 0; tnh < 2; tnh++) {
                uint32_t addr = bsb + bLaneOff +
                    (uint32_t)((kh * 16 * BPAD + warp_n + tnh * 16) * 2);
                uint32_t r0, r1, r2, r3;
                asm volatile(
                    "ldmatrix.sync.aligned.m8n8.x4.trans.shared.b16 {%0,%1,%2,%3}, [%4];"
                    : "=r"(r0), "=r"(r1), "=r"(r2), "=r"(r3)
                    : "r"(addr));
                b[tnh * 2][0] = r0; b[tnh * 2][1] = r1;
                b[tnh * 2 + 1][0] = r2; b[tnh * 2 + 1][1] = r3;
            }
#pragma unroll
            for (int tm = 0; tm < 4; tm++)
#pragma unroll
                for (int tn = 0; tn < 4; tn++) {
                    asm volatile(
                        "mma.sync.aligned.m16n8k16.row.col.f32.bf16.bf16.f32 "
                        "{%0,%1,%2,%3}, {%4,%5,%6,%7}, {%8,%9}, {%0,%1,%2,%3};"
                        : "+f"(c[tm][tn][0]), "+f"(c[tm][tn][1]),
                          "+f"(c[tm][tn][2]), "+f"(c[tm][tn][3])
                        : "r"(a[tm][0]), "r"(a[tm][1]), "r"(a[tm][2]), "r"(a[tm][3]),
                          "r"(b[tn][0]), "r"(b[tn][1]));
                }
        }
    }

    float* st = reinterpret_cast<float*>(smg);
#pragma unroll 1
    for (int rnd = 0; rnd < 2; rnd++) {
        __syncthreads();
        if ((wid >> 2) == rnd) {
            const int mb = lane >> 2;
            const int nb = (lane & 3) * 2;
#pragma unroll
            for (int tm = 0; tm < 4; tm++) {
                int ml = tm * 16 + mb;
#pragma unroll
                for (int tn = 0; tn < 4; tn++) {
                    int n0 = warp_n + tn * 8 + nb;
                    *reinterpret_cast<float2*>(&st[ml * EPAD + n0]) =
                        make_float2(c[tm][tn][0], c[tm][tn][1]);
                    *reinterpret_cast<float2*>(&st[(ml + 8) * EPAD + n0]) =
                        make_float2(c[tm][tn][2], c[tm][tn][3]);
                }
            }
        }
        __syncthreads();
        const int c4 = (tid & 31) * 4;
        float4 bv = *reinterpret_cast<const float4*>(&bias[bcol + c4]);
#pragma unroll
        for (int i = 0; i < 8; i++) {
            int row = i * 8 + (tid >> 5);
            float4 v = *reinterpret_cast<float4*>(&st[row * EPAD + c4]);
            v.x += bv.x; v.y += bv.y; v.z += bv.z; v.w += bv.w;
            *reinterpret_cast<float4*>(
                &g_gx[(size_t)(brow + rnd * 64 + row) * G3 + bcol + c4]) = v;
        }
    }
}

// ===========================================================================
// Kernel B: HMMA GRU recurrence (R14 structure) with 9 INDEPENDENT
// accumulators (3 per gate: hi*hi, lo*hi, hi*lo) — chain depth 48 -> 16,
// ILP 3 -> 9. Everything else identical to the passing R14 kernel.
// ===========================================================================
#define TPB_B 256
#define WS_BYTES (256 * 200 * 2)
#define HB_OFF   WS_BYTES
#define HB_PAR   16384
#define MBAR_OFF (HB_OFF + 2 * HB_PAR)
#define SMEM_B_BYTES (MBAR_OFF + 16)

__device__ __forceinline__ float sigmoidf_fast(float x) {
    return __fdividef(1.0f, 1.0f + __expf(-x));
}
__device__ __forceinline__ float tanhf_fast(float x) {
    x = fminf(fmaxf(x, -15.f), 15.f);
    float e = __expf(2.f * x);
    return __fdividef(e - 1.f, e + 1.f);
}

__device__ __forceinline__ void mbar_wait_parity(uint32_t mbar, uint32_t parity) {
    asm volatile(
        "{\n\t"
        ".reg .pred P;\n\t"
        "WAIT_%=:\n\t"
        "mbarrier.try_wait.parity.acquire.cluster.shared::cta.b64 P, [%0], %1, 0x989680;\n\t"
        "@P bra DONE_%=;\n\t"
        "bra WAIT_%=;\n\t"
        "DONE_%=:\n\t"
        "}"
        :: "r"(mbar), "r"(parity) : "memory");
}

#define MMA_BF16(C, A0, A1, A2, A3, B0, B1)                                  \
    asm volatile(                                                            \
        "mma.sync.aligned.m16n8k16.row.col.f32.bf16.bf16.f32 "               \
        "{%0,%1,%2,%3}, {%4,%5,%6,%7}, {%8,%9}, {%0,%1,%2,%3};"              \
        : "+f"((C)[0]), "+f"((C)[1]), "+f"((C)[2]), "+f"((C)[3])             \
        : "r"(A0), "r"(A1), "r"(A2), "r"(A3), "r"(B0), "r"(B1))

__global__ void __cluster_dims__(4, 1, 1) __launch_bounds__(TPB_B, 1)
gru_rec_kernel(const float* __restrict__ mask,
               const float* __restrict__ Whh,
               const float* __restrict__ bhh,
               float* __restrict__ out)
{
    extern __shared__ char smc[];
    __nv_bfloat16* Ws16 = reinterpret_cast<__nv_bfloat16*>(smc);

    const int tid  = threadIdx.x;
    const int lane = tid & 31;
    const int w    = tid >> 5;
    uint32_t rank;
    asm("mov.u32 %0, %%cluster_ctarank;" : "=r"(rank));
    const int ci = (int)blockIdx.x >> 2;

    uint32_t smB;
    asm("{ .reg .u64 t; cvta.to.shared.u64 t, %1; cvt.u32.u64 %0, t; }"
        : "=r"(smB) : "l"(smc));
    const uint32_t mbar_u32 = smB + MBAR_OFF;

    if (tid == 0) {
        asm volatile("mbarrier.init.shared.b64 [%0], 1;" :: "r"(mbar_u32) : "memory");
        asm volatile("mbarrier.init.shared.b64 [%0], 1;" :: "r"(mbar_u32 + 8) : "memory");
        asm volatile("mbarrier.arrive.expect_tx.shared.b64 _, [%0], 12288;"
                     :: "r"(mbar_u32) : "memory");
        asm volatile("mbarrier.arrive.expect_tx.shared.b64 _, [%0], 12288;"
                     :: "r"(mbar_u32 + 8) : "memory");
    }

    // ---- stage W_hh HI into Ws, ldmatrix fragments into registers ----
    for (int idx = tid; idx < 256 * 192; idx += TPB_B) {
        int k = idx / 192;
        int n = idx - k * 192;
        int g = n >> 6;
        int jl = n & 63;
        float v = Whh[k * G3 + g * 256 + (int)rank * 64 + jl];
        Ws16[k * 200 + n] = __float2bfloat16(v);
    }
    __syncthreads();

    uint32_t bhi[3][16][2];
#pragma unroll
    for (int g = 0; g < 3; g++)
#pragma unroll
        for (int s = 0; s < 16; s++) {
            uint32_t addr = smB +
                (uint32_t)(((s * 16 + (lane & 15)) * 200 + g * 64 + w * 8) * 2);
            asm volatile(
                "ldmatrix.sync.aligned.m8n8.x2.trans.shared.b16 {%0,%1}, [%2];"
                : "=r"(bhi[g][s][0]), "=r"(bhi[g][s][1]) : "r"(addr));
        }
    __syncthreads();

    // ---- stage W_hh LO into Ws (per-step ldmatrix source) ----
    for (int idx = tid; idx < 256 * 192; idx += TPB_B) {
        int k = idx / 192;
        int n = idx - k * 192;
        int g = n >> 6;
        int jl = n & 63;
        float v = Whh[k * G3 + g * 256 + (int)rank * 64 + jl];
        __nv_bfloat16 h = __float2bfloat16(v);
        Ws16[k * 200 + n] = __float2bfloat16(v - __bfloat162float(h));
    }
    for (int idx = tid; idx < (2 * HB_PAR) / 4; idx += TPB_B)
        reinterpret_cast<uint32_t*>(smc + HB_OFF)[idx] = 0u;

    const int r   = lane >> 2;
    const int jl0 = 8 * w + (lane & 3) * 2;
    const int jge = (int)rank * 64 + jl0;
    const int bbg0 = ci * 16 + r;
    const int bbg1 = bbg0 + 8;

    const float2 bhr2 = *reinterpret_cast<const float2*>(&bhh[jge]);
    const float2 bhz2 = *reinterpret_cast<const float2*>(&bhh[256 + jge]);
    const float2 bhn2 = *reinterpret_cast<const float2*>(&bhh[512 + jge]);
    const float* m_p0 = mask + (size_t)bbg0 * Ssz;
    const float* m_p1 = mask + (size_t)bbg1 * Ssz;

    float hp[4] = {0.f, 0.f, 0.f, 0.f};

    __syncthreads();
    asm volatile("barrier.cluster.arrive.aligned;" ::: "memory");
    asm volatile("barrier.cluster.wait.aligned;" ::: "memory");

    int ph0 = 0, ph1 = 0;

    const uint32_t aRow = (uint32_t)((lane & 15) * 256);
    const int aHalf = lane >> 4;
    const int aXor  = lane & 7;
    const uint32_t stsOff0 = (uint32_t)(((w ^ (r & 7)) * 16) + (lane & 3) * 4);

    for (int t = 0; t < Ssz; t++) {
        const int p = t & 1;

        const float* gxt0 = g_gx + ((size_t)bbg0 * Ssz + t) * G3 + jge;
        const float* gxt1 = g_gx + ((size_t)bbg1 * Ssz + t) * G3 + jge;
        float2 gr0 = __ldcs(reinterpret_cast<const float2*>(gxt0));
        float2 gz0 = __ldcs(reinterpret_cast<const float2*>(gxt0 + 256));
        float2 gn0 = __ldcs(reinterpret_cast<const float2*>(gxt0 + 512));
        float2 gr1 = __ldcs(reinterpret_cast<const float2*>(gxt1));
        float2 gz1 = __ldcs(reinterpret_cast<const float2*>(gxt1 + 256));
        float2 gn1 = __ldcs(reinterpret_cast<const float2*>(gxt1 + 512));
        float mt0 = __ldg(m_p0 + t);
        float mt1 = __ldg(m_p1 + t);

        if (t > 0) {
            uint32_t mb = mbar_u32 + (uint32_t)(p * 8);
            if (p == 0) { mbar_wait_parity(mb, ph0); ph0 ^= 1; }
            else        { mbar_wait_parity(mb, ph1); ph1 ^= 1; }
            if (tid == 0 && t + 2 < Ssz)
                asm volatile("mbarrier.arrive.expect_tx.shared.b64 _, [%0], 12288;"
                             :: "r"(mb) : "memory");
        }

        // ---- mma chains: 9 independent accumulators (3 per gate) ----
        float Ca[3][4], Cb[3][4], Cc[3][4];
#pragma unroll
        for (int g = 0; g < 3; g++)
#pragma unroll
            for (int q = 0; q < 4; q++) {
                Ca[g][q] = 0.f; Cb[g][q] = 0.f; Cc[g][q] = 0.f;
            }

        const uint32_t hbp = smB + (uint32_t)(HB_OFF + p * HB_PAR);
#pragma unroll
        for (int s = 0; s < 16; s++) {
            uint32_t chunk = (uint32_t)(((((s & 3) * 2 + aHalf) ^ aXor)) * 16);
            uint32_t aaddr = hbp + (uint32_t)((s >> 2) * 4096) + aRow + chunk;
            uint32_t ahi[4], alo[4];
            asm volatile(
                "ldmatrix.sync.aligned.m8n8.x4.shared.b16 {%0,%1,%2,%3}, [%4];"
                : "=r"(ahi[0]), "=r"(ahi[1]), "=r"(ahi[2]), "=r"(ahi[3])
                : "r"(aaddr));
            asm volatile(
                "ldmatrix.sync.aligned.m8n8.x4.shared.b16 {%0,%1,%2,%3}, [%4];"
                : "=r"(alo[0]), "=r"(alo[1]), "=r"(alo[2]), "=r"(alo[3])
                : "r"(aaddr + 128));
            uint32_t bl[3][2];
#pragma unroll
            for (int g = 0; g < 3; g++) {
                uint32_t baddr = smB +
                    (uint32_t)(((s * 16 + (lane & 15)) * 200 + g * 64 + w * 8) * 2);
                asm volatile(
                    "ldmatrix.sync.aligned.m8n8.x2.trans.shared.b16 {%0,%1}, [%2];"
                    : "=r"(bl[g][0]), "=r"(bl[g][1]) : "r"(baddr));
            }
#pragma unroll
            for (int g = 0; g < 3; g++) {
                MMA_BF16(Ca[g], ahi[0], ahi[1], ahi[2], ahi[3],
                         bhi[g][s][0], bhi[g][s][1]);
                MMA_BF16(Cb[g], alo[0], alo[1], alo[2], alo[3],
                         bhi[g][s][0], bhi[g][s][1]);
                MMA_BF16(Cc[g], ahi[0], ahi[1], ahi[2], ahi[3],
                         bl[g][0], bl[g][1]);
            }
        }

        // ---- gates on summed fragments ----
        const uint32_t hbn = smB + (uint32_t)(HB_OFF + (p ^ 1) * HB_PAR) +
                             rank * 4096u;
#pragma unroll
        for (int rr = 0; rr < 2; rr++) {
            float2 gr = rr ? gr1 : gr0;
            float2 gz = rr ? gz1 : gz0;
            float2 gn = rr ? gn1 : gn0;
            float mt  = rr ? mt1 : mt0;
            float hout[2];
#pragma unroll
            for (int jj = 0; jj < 2; jj++) {
                int q = rr * 2 + jj;
                float Cr = Ca[0][q] + Cb[0][q] + Cc[0][q];
                float Cz = Ca[1][q] + Cb[1][q] + Cc[1][q];
                float Cn = Ca[2][q] + Cb[2][q] + Cc[2][q];
                float gxr = jj ? gr.y : gr.x;
                float gxz = jj ? gz.y : gz.x;
                float gxn = jj ? gn.y : gn.x;
                float br = jj ? bhr2.y : bhr2.x;
                float bz = jj ? bhz2.y : bhz2.x;
                float bn = jj ? bhn2.y : bhn2.x;
                float hold = hp[q];
                float rg = sigmoidf_fast(gxr + Cr + br);
                float zg = sigmoidf_fast(gxz + Cz + bz);
                float ng = tanhf_fast(fmaf(rg, Cn + bn, gxn));
                float hnew = fmaf(zg, hold - ng, ng);
                float ho = fmaf(mt, hnew - hold, hold);
                hp[q] = ho;
                hout[jj] = ho;
            }
            int bb = rr ? bbg1 : bbg0;
            *reinterpret_cast<float2*>(
                &out[((size_t)bb * Ssz + t) * Hsz + jge]) =
                make_float2(hout[0], hout[1]);

            __nv_bfloat16 h0 = __float2bfloat16(hout[0]);
            __nv_bfloat16 h1 = __float2bfloat16(hout[1]);
            __nv_bfloat16 l0 = __float2bfloat16(hout[0] - __bfloat162float(h0));
            __nv_bfloat16 l1 = __float2bfloat16(hout[1] - __bfloat162float(h1));
            uint32_t hiw = (uint32_t)*reinterpret_cast<unsigned short*>(&h0) |
                           ((uint32_t)*reinterpret_cast<unsigned short*>(&h1) << 16);
            uint32_t low = (uint32_t)*reinterpret_cast<unsigned short*>(&l0) |
                           ((uint32_t)*reinterpret_cast<unsigned short*>(&l1) << 16);
            uint32_t rowb = hbn + (uint32_t)((r + rr * 8) * 256) + stsOff0;
            asm volatile("st.shared.b32 [%0], %1;" :: "r"(rowb), "r"(hiw) : "memory");
            asm volatile("st.shared.b32 [%0], %1;" :: "r"(rowb + 128), "r"(low) : "memory");
        }

        if (t < Ssz - 1) {
            __syncthreads();

            if (tid < 3) {
                asm volatile("fence.proxy.async.shared::cta;" ::: "memory");
                int pp = ((int)rank + 1 + tid) & 3;
                uint32_t src = hbn;
                uint32_t mb_local = mbar_u32 + (uint32_t)(((t + 1) & 1) * 8);
                uint32_t dst_r, mb_r;
                asm volatile("mapa.shared::cluster.u32 %0, %1, %2;"
                             : "=r"(dst_r) : "r"(src), "r"(pp));
                asm volatile("mapa.shared::cluster.u32 %0, %1, %2;"
                             : "=r"(mb_r) : "r"(mb_local), "r"(pp));
                asm volatile(
                    "cp.async.bulk.shared::cluster.shared::cta."
                    "mbarrier::complete_tx::bytes [%0], [%1], %2, [%3];"
                    :: "r"(dst_r), "r"(src), "r"(4096), "r"(mb_r) : "memory");
            }
        }
    }
}

// ---------------------------------------------------------------------------
extern "C" void kernel_launch(void* const* d_in, const int* in_sizes, int n_in,
                              void* d_out, int out_size)
{
    (void)in_sizes; (void)n_in; (void)out_size;
    const float* x    = (const float*)d_in[0];
    const float* mask = (const float*)d_in[1];
    const float* Wih  = (const float*)d_in[2];
    const float* Whh  = (const float*)d_in[3];
    const float* bih  = (const float*)d_in[4];
    const float* bhh  = (const float*)d_in[5];
    float* out = (float*)d_out;

    cudaFuncSetAttribute(gru_rec_kernel,
                         cudaFuncAttributeMaxDynamicSharedMemorySize,
                         SMEM_B_BYTES);

    split_x_kernel<<<(Bsz * Ssz * Dsz) / (256 * 8), 256>>>(x);
    split_w_kernel<<<(Dsz * G3) / (256 * 8), 256>>>(Wih);

    dim3 gridA(G3 / 128, (Bsz * Ssz) / 128);
    gemm_gx_mma<<<gridA, 256, SMEM_GEMM>>>(bih);

    gru_rec_kernel<<<32, TPB_B, SMEM_B_BYTES>>>(mask, Whh, bhh, out);
}

// round 16
// speedup vs baseline: 1.0990x; 1.0990x over previous
#include <cuda_runtime.h>
#include <cuda_bf16.h>
#include <cstdint>
#include <cstddef>

#define Bsz 128
#define Ssz 1024
#define Dsz 256
#define Hsz 256
#define G3  768

// Scratch: gx (fp32) + bf16 hi/lo splits of X and W_ih
__device__ float g_gx[(size_t)Bsz * Ssz * G3];
__device__ __nv_bfloat16 g_xhi[(size_t)Bsz * Ssz * Dsz];
__device__ __nv_bfloat16 g_xlo[(size_t)Bsz * Ssz * Dsz];
__device__ __nv_bfloat16 g_whi[Dsz * G3];
__device__ __nv_bfloat16 g_wlo[Dsz * G3];

typedef unsigned long long ull;

__device__ __forceinline__ ull pk(float a, float b) {
    ull r;
    asm("mov.b64 %0, {%1, %2};" : "=l"(r) : "f"(a), "f"(b));
    return r;
}
__device__ __forceinline__ void fma2(ull& acc, ull a, ull b) {
    asm("fma.rn.f32x2 %0, %1, %2, %0;" : "+l"(acc) : "l"(a), "l"(b));
}

// ===========================================================================
// Split kernels: fp32 -> bf16 (hi) + bf16 (residual lo)
// ===========================================================================
__device__ __forceinline__ void split8(const float* src, __nv_bfloat16* dhi,
                                       __nv_bfloat16* dlo, size_t i) {
    float4 v0 = *reinterpret_cast<const float4*>(src + i);
    float4 v1 = *reinterpret_cast<const float4*>(src + i + 4);
    float v[8] = {v0.x, v0.y, v0.z, v0.w, v1.x, v1.y, v1.z, v1.w};
    unsigned h[4], l[4];
#pragma unroll
    for (int e = 0; e < 4; e++) {
        __nv_bfloat16 h0 = __float2bfloat16(v[e * 2]);
        __nv_bfloat16 h1 = __float2bfloat16(v[e * 2 + 1]);
        __nv_bfloat16 l0 = __float2bfloat16(v[e * 2]     - __bfloat162float(h0));
        __nv_bfloat16 l1 = __float2bfloat16(v[e * 2 + 1] - __bfloat162float(h1));
        h[e] = (unsigned)*reinterpret_cast<unsigned short*>(&h0) |
               ((unsigned)*reinterpret_cast<unsigned short*>(&h1) << 16);
        l[e] = (unsigned)*reinterpret_cast<unsigned short*>(&l0) |
               ((unsigned)*reinterpret_cast<unsigned short*>(&l1) << 16);
    }
    *reinterpret_cast<uint4*>(dhi + i) = make_uint4(h[0], h[1], h[2], h[3]);
    *reinterpret_cast<uint4*>(dlo + i) = make_uint4(l[0], l[1], l[2], l[3]);
}

__global__ __launch_bounds__(256) void split_x_kernel(const float* __restrict__ X) {
    size_t i = ((size_t)blockIdx.x * 256 + threadIdx.x) * 8;
    split8(X, g_xhi, g_xlo, i);
}
__global__ __launch_bounds__(256) void split_w_kernel(const float* __restrict__ W) {
    size_t i = ((size_t)blockIdx.x * 256 + threadIdx.x) * 8;
    split8(W, g_whi, g_wlo, i);
}

// ===========================================================================
// Kernel A: gx = X @ W_ih + b_ih via mma.sync bf16 (R13, passing, ~510us)
// ===========================================================================
#define APAD 40
#define BPAD 136
#define AS_BUF (128 * APAD * 2)
#define BS_BUF (32 * BPAD * 2)
#define BS_BASE (2 * AS_BUF)
#define SMEM_GEMM (BS_BASE + 2 * BS_BUF)
#define EPAD 136

__global__ __launch_bounds__(256, 2) void gemm_gx_mma(const float* __restrict__ bias)
{
    extern __shared__ char smg[];
    const int tid  = threadIdx.x;
    const int lane = tid & 31;
    const int wid  = tid >> 5;
    const int brow = blockIdx.y * 128;
    const int bcol = blockIdx.x * 128;
    const int warp_m = (wid >> 2) * 64;
    const int warp_n = (wid & 3) * 32;

    float c[4][4][4];
#pragma unroll
    for (int tm = 0; tm < 4; tm++)
#pragma unroll
        for (int tn = 0; tn < 4; tn++)
#pragma unroll
            for (int r = 0; r < 4; r++) c[tm][tn][r] = 0.f;

    int arow[2], ak8[2], bkr[2], bn8[2];
#pragma unroll
    for (int ch = 0; ch < 2; ch++) {
        int id = tid + ch * 256;
        arow[ch] = id >> 2;
        ak8[ch]  = (id & 3) * 8;
        bkr[ch]  = id >> 4;
        bn8[ch]  = (id & 15) * 8;
    }

    uint32_t smB;
    asm("{ .reg .u64 t; cvta.to.shared.u64 t, %1; cvt.u32.u64 %0, t; }"
        : "=r"(smB) : "l"(smg));

    const uint32_t aLaneOff = (uint32_t)(((lane & 15) * APAD + (lane >> 4) * 8) * 2);
    const uint32_t bLaneOff = (uint32_t)(((((lane >> 3) & 1) * 8 + (lane & 7)) * BPAD
                                          + (lane >> 4) * 8) * 2);

    uint4 ra[2], rb[2];
#pragma unroll
    for (int ch = 0; ch < 2; ch++) {
        ra[ch] = *reinterpret_cast<const uint4*>(
            &g_xhi[(size_t)(brow + arow[ch]) * Dsz + ak8[ch]]);
        rb[ch] = *reinterpret_cast<const uint4*>(
            &g_whi[(size_t)bkr[ch] * G3 + bcol + bn8[ch]]);
    }

#pragma unroll 1
    for (int it = 0; it < 24; it++) {
        const int buf = it & 1;
        __nv_bfloat16* As = reinterpret_cast<__nv_bfloat16*>(smg + buf * AS_BUF);
        __nv_bfloat16* Bs = reinterpret_cast<__nv_bfloat16*>(smg + BS_BASE + buf * BS_BUF);

#pragma unroll
        for (int ch = 0; ch < 2; ch++) {
            *reinterpret_cast<uint4*>(&As[arow[ch] * APAD + ak8[ch]]) = ra[ch];
            *reinterpret_cast<uint4*>(&Bs[bkr[ch] * BPAD + bn8[ch]]) = rb[ch];
        }
        __syncthreads();

        if (it + 1 < 24) {
            int p  = (it + 1) >> 3;
            int k0 = ((it + 1) & 7) * 32;
            const __nv_bfloat16* Ag = (p < 2) ? g_xhi : g_xlo;
            const __nv_bfloat16* Bg = (p == 1) ? g_wlo : g_whi;
#pragma unroll
            for (int ch = 0; ch < 2; ch++) {
                ra[ch] = *reinterpret_cast<const uint4*>(
                    &Ag[(size_t)(brow + arow[ch]) * Dsz + k0 + ak8[ch]]);
                rb[ch] = *reinterpret_cast<const uint4*>(
                    &Bg[(size_t)(k0 + bkr[ch]) * G3 + bcol + bn8[ch]]);
            }
        }

        const uint32_t asb = smB + (uint32_t)(buf * AS_BUF);
        const uint32_t bsb = smB + (uint32_t)(BS_BASE + buf * BS_BUF);
#pragma unroll
        for (int kh = 0; kh < 2; kh++) {
            uint32_t a[4][4];
#pragma unroll
            for (int tm = 0; tm < 4; tm++) {
                uint32_t addr = asb + aLaneOff +
                    (uint32_t)(((warp_m + tm * 16) * APAD + kh * 16) * 2);
                asm volatile(
                    "ldmatrix.sync.aligned.m8n8.x4.shared.b16 {%0,%1,%2,%3}, [%4];"
                    : "=r"(a[tm][0]), "=r"(a[tm][1]), "=r"(a[tm][2]), "=r"(a[tm][3])
                    : "r"(addr));
            }
            uint32_t b[4][2];
#pragma unroll
            for (int tnh = 0; tnh < 2; tnh++) {
                uint32_t addr = bsb + bLaneOff +
                    (uint32_t)((kh * 16 * BPAD + warp_n + tnh * 16) * 2);
                uint32_t r0, r1, r2, r3;
                asm volatile(
                    "ldmatrix.sync.aligned.m8n8.x4.trans.shared.b16 {%0,%1,%2,%3}, [%4];"
                    : "=r"(r0), "=r"(r1), "=r"(r2), "=r"(r3)
                    : "r"(addr));
                b[tnh * 2][0] = r0; b[tnh * 2][1] = r1;
                b[tnh * 2 + 1][0] = r2; b[tnh * 2 + 1][1] = r3;
            }
#pragma unroll
            for (int tm = 0; tm < 4; tm++)
#pragma unroll
                for (int tn = 0; tn < 4; tn++) {
                    asm volatile(
                        "mma.sync.aligned.m16n8k16.row.col.f32.bf16.bf16.f32 "
                        "{%0,%1,%2,%3}, {%4,%5,%6,%7}, {%8,%9}, {%0,%1,%2,%3};"
                        : "+f"(c[tm][tn][0]), "+f"(c[tm][tn][1]),
                          "+f"(c[tm][tn][2]), "+f"(c[tm][tn][3])
                        : "r"(a[tm][0]), "r"(a[tm][1]), "r"(a[tm][2]), "r"(a[tm][3]),
                          "r"(b[tn][0]), "r"(b[tn][1]));
                }
        }
    }

    float* st = reinterpret_cast<float*>(smg);
#pragma unroll 1
    for (int rnd = 0; rnd < 2; rnd++) {
        __syncthreads();
        if ((wid >> 2) == rnd) {
            const int mb = lane >> 2;
            const int nb = (lane & 3) * 2;
#pragma unroll
            for (int tm = 0; tm < 4; tm++) {
                int ml = tm * 16 + mb;
#pragma unroll
                for (int tn = 0; tn < 4; tn++) {
                    int n0 = warp_n + tn * 8 + nb;
                    *reinterpret_cast<float2*>(&st[ml * EPAD + n0]) =
                        make_float2(c[tm][tn][0], c[tm][tn][1]);
                    *reinterpret_cast<float2*>(&st[(ml + 8) * EPAD + n0]) =
                        make_float2(c[tm][tn][2], c[tm][tn][3]);
                }
            }
        }
        __syncthreads();
        const int c4 = (tid & 31) * 4;
        float4 bv = *reinterpret_cast<const float4*>(&bias[bcol + c4]);
#pragma unroll
        for (int i = 0; i < 8; i++) {
            int row = i * 8 + (tid >> 5);
            float4 v = *reinterpret_cast<float4*>(&st[row * EPAD + c4]);
            v.x += bv.x; v.y += bv.y; v.z += bv.z; v.w += bv.w;
            *reinterpret_cast<float4*>(
                &g_gx[(size_t)(brow + rnd * 64 + row) * G3 + bcol + c4]) = v;
        }
    }
}

// ===========================================================================
// Kernel B: persistent GRU recurrence — R8 FFMA core, INTERLEAVING TWO
// independent 2-batch chains per cluster so each group's copy flight +
// mbar turnaround hides under the other group's compute phase.
// ===========================================================================
#define TPB_B 256
#define NKREG 20
#define NKSM  12

// ull units:
// Ws2[8][12][3][32]=9216 | hb2[2g][2p][256k][2b]=2048 | red[8][2][3][32]=1536
// | stage[2g][2p][128]=512
#define ULL_W     0
#define ULL_H     9216
#define ULL_RED   (ULL_H + 2048)      // 11264
#define ULL_STAGE (ULL_RED + 1536)    // 12800
#define ULL_TOT   (ULL_STAGE + 512)   // 13312
#define SMEM_B_BYTES (ULL_TOT * 8 + 32)

__device__ __forceinline__ float sigmoidf_fast(float x) {
    return __fdividef(1.0f, 1.0f + __expf(-x));
}
__device__ __forceinline__ float tanhf_fast(float x) {
    x = fminf(fmaxf(x, -15.f), 15.f);
    float e = __expf(2.f * x);
    return __fdividef(e - 1.f, e + 1.f);
}

__device__ __forceinline__ void mbar_wait_parity(uint32_t mbar, uint32_t parity) {
    asm volatile(
        "{\n\t"
        ".reg .pred P;\n\t"
        "WAIT_%=:\n\t"
        "mbarrier.try_wait.parity.acquire.cluster.shared::cta.b64 P, [%0], %1, 0x989680;\n\t"
        "@P bra DONE_%=;\n\t"
        "bra WAIT_%=;\n\t"
        "DONE_%=:\n\t"
        "}"
        :: "r"(mbar), "r"(parity) : "memory");
}

__global__ void __cluster_dims__(4, 1, 1) __launch_bounds__(TPB_B, 1)
gru_rec_kernel(const float* __restrict__ mask,
               const float* __restrict__ Whh,
               const float* __restrict__ bhh,
               float* __restrict__ out)
{
    extern __shared__ ull smu[];
    ull* Ws2 = smu + ULL_W;

    const int tid = threadIdx.x;
    uint32_t rank;
    asm("mov.u32 %0, %%cluster_ctarank;" : "=r"(rank));
    const int ci = (int)blockIdx.x >> 2;

    uint32_t smB;
    asm("{ .reg .u64 t; cvta.to.shared.u64 t, %1; cvt.u32.u64 %0, t; }"
        : "=r"(smB) : "l"(smu));
    const uint32_t mbar_u32 = smB + (uint32_t)(ULL_TOT * 8);

    if (tid == 0) {
#pragma unroll
        for (int m = 0; m < 4; m++) {
            asm volatile("mbarrier.init.shared.b64 [%0], 1;"
                         :: "r"(mbar_u32 + m * 8) : "memory");
            asm volatile("mbarrier.arrive.expect_tx.shared.b64 _, [%0], 4096;"
                         :: "r"(mbar_u32 + m * 8) : "memory");
        }
    }

    for (int idx = tid; idx < 8 * NKSM * 3 * 32; idx += TPB_B) {
        int jp_ = idx & 31;
        int g   = (idx >> 5) % 3;
        int kk  = (idx / 96) % NKSM;
        int kq_ = idx / (96 * NKSM);
        int k   = kq_ * 32 + NKREG + kk;
        int base = k * G3 + g * 256 + (int)rank * 64 + jp_ * 2;
        Ws2[idx] = pk(Whh[base], Whh[base + 1]);
    }
    for (int idx = tid; idx < 2048; idx += TPB_B) smu[ULL_H + idx] = 0ull;

    const int kq = tid >> 5;
    const int jp = tid & 31;
    const int k0 = kq * 32;
    const int jg0 = (int)rank * 64 + jp * 2;

    ull wr[NKREG], wz[NKREG], wn[NKREG];
#pragma unroll
    for (int kk = 0; kk < NKREG; kk++) {
        int k = k0 + kk;
        wr[kk] = pk(Whh[k * G3 + jg0],       Whh[k * G3 + jg0 + 1]);
        wz[kk] = pk(Whh[k * G3 + 256 + jg0], Whh[k * G3 + 256 + jg0 + 1]);
        wn[kk] = pk(Whh[k * G3 + 512 + jg0], Whh[k * G3 + 512 + jg0 + 1]);
    }

    const bool ew = (tid < 128);
    const int je = tid & 63;
    const int be = (tid >> 6) & 1;
    const int jge = (int)rank * 64 + je;
    float bhr = 0.f, bhz = 0.f, bhn = 0.f;
    const float* gx_pg[2] = {nullptr, nullptr};
    const float* m_pg[2]  = {nullptr, nullptr};
    float* out_pg[2] = {nullptr, nullptr};
    if (ew) {
        bhr = bhh[jge];
        bhz = bhh[256 + jge];
        bhn = bhh[512 + jge];
#pragma unroll
        for (int g = 0; g < 2; g++) {
            int bbg = ci * 4 + g * 2 + be;
            gx_pg[g]  = g_gx + (size_t)bbg * Ssz * G3;
            m_pg[g]   = mask + (size_t)bbg * Ssz;
            out_pg[g] = out + (size_t)bbg * Ssz * Hsz + jge;
        }
    }

    __syncthreads();
    asm volatile("barrier.cluster.arrive.aligned;" ::: "memory");
    asm volatile("barrier.cluster.wait.aligned;" ::: "memory");

    int ph[2][2] = {{0, 0}, {0, 0}};

    for (int t = 0; t < Ssz; t++) {
        const int mi = t & 1;
        const int pn = mi ^ 1;

        float gxr[2], gxz[2], gxn[2], mt[2];
        if (ew) {
#pragma unroll
            for (int g = 0; g < 2; g++) {
                const float* gxt = gx_pg[g] + (size_t)t * G3;
                gxr[g] = __ldcs(gxt + jge);
                gxz[g] = __ldcs(gxt + 256 + jge);
                gxn[g] = __ldcs(gxt + 512 + jge);
                mt[g]  = __ldg(m_pg[g] + t);
            }
        }

#pragma unroll
        for (int g = 0; g < 2; g++) {
            if (t > 0) {
                uint32_t mb = mbar_u32 + (uint32_t)((g * 2 + mi) * 8);
                mbar_wait_parity(mb, (uint32_t)ph[g][mi]);
                ph[g][mi] ^= 1;
                if (tid == 0 && t + 2 < Ssz)
                    asm volatile("mbarrier.arrive.expect_tx.shared.b64 _, [%0], 4096;"
                                 :: "r"(mb) : "memory");
            }

            const ull* hG = smu + ULL_H + g * 1024 + mi * 512;
            float hold = 0.f;
            if (ew)
                hold = reinterpret_cast<const float*>(&hG[jge * 2 + be])[0];

            ull ar[2] = {0, 0}, az[2] = {0, 0}, an[2] = {0, 0};
            const ull* hK = hG + k0 * 2;

#pragma unroll
            for (int kk = 0; kk < NKREG; kk++) {
                ulonglong2 h2 = *reinterpret_cast<const ulonglong2*>(hK + kk * 2);
                fma2(ar[0], h2.x, wr[kk]); fma2(ar[1], h2.y, wr[kk]);
                fma2(az[0], h2.x, wz[kk]); fma2(az[1], h2.y, wz[kk]);
                fma2(an[0], h2.x, wn[kk]); fma2(an[1], h2.y, wn[kk]);
            }
#pragma unroll
            for (int kk2 = 0; kk2 < NKSM; kk2++) {
                const ull* wb = Ws2 + ((kq * NKSM + kk2) * 3) * 32 + jp;
                ull w_r = wb[0];
                ull w_z = wb[32];
                ull w_n = wb[64];
                ulonglong2 h2 = *reinterpret_cast<const ulonglong2*>(
                    hK + (NKREG + kk2) * 2);
                fma2(ar[0], h2.x, w_r); fma2(ar[1], h2.y, w_r);
                fma2(az[0], h2.x, w_z); fma2(az[1], h2.y, w_z);
                fma2(an[0], h2.x, w_n); fma2(an[1], h2.y, w_n);
            }

            {
                ull* rb = smu + ULL_RED + kq * 192 + jp;
#pragma unroll
                for (int b = 0; b < 2; b++) {
                    rb[b * 96]      = ar[b];
                    rb[b * 96 + 32] = az[b];
                    rb[b * 96 + 64] = an[b];
                }
            }
            __syncthreads();

            if (ew) {
                float ghr = bhr, ghz = bhz, ghn = bhn;
                const float* redf = reinterpret_cast<const float*>(smu + ULL_RED);
                const int fb = be * 192 + je;
#pragma unroll
                for (int q = 0; q < 8; q++) {
                    const float* rp = redf + q * 384 + fb;
                    ghr += rp[0];
                    ghz += rp[64];
                    ghn += rp[128];
                }
                float r = sigmoidf_fast(gxr[g] + ghr);
                float z = sigmoidf_fast(gxz[g] + ghz);
                float n = tanhf_fast(fmaf(r, ghn, gxn[g]));
                float hnew = fmaf(z, hold - n, n);
                float hout = fmaf(mt[g], hnew - hold, hold);
                out_pg[g][(size_t)t * Hsz] = hout;

                smu[ULL_STAGE + g * 256 + pn * 128 + je * 2 + be] = pk(hout, hout);
            }
            __syncthreads();

            if (t < Ssz - 1 && tid < 4) {
                asm volatile("fence.proxy.async.shared::cta;" ::: "memory");
                uint32_t src = smB +
                    (uint32_t)((ULL_STAGE + g * 256 + pn * 128) * 8);
                uint32_t dst_local = smB +
                    (uint32_t)((ULL_H + g * 1024 + pn * 512 + (int)rank * 128) * 8);
                uint32_t mb_local = mbar_u32 + (uint32_t)((g * 2 + pn) * 8);
                uint32_t dst_r, mb_r;
                asm volatile("mapa.shared::cluster.u32 %0, %1, %2;"
                             : "=r"(dst_r) : "r"(dst_local), "r"(tid));
                asm volatile("mapa.shared::cluster.u32 %0, %1, %2;"
                             : "=r"(mb_r) : "r"(mb_local), "r"(tid));
                asm volatile(
                    "cp.async.bulk.shared::cluster.shared::cta."
                    "mbarrier::complete_tx::bytes [%0], [%1], %2, [%3];"
                    :: "r"(dst_r), "r"(src), "r"(1024), "r"(mb_r) : "memory");
            }
        }
    }
}

// ---------------------------------------------------------------------------
extern "C" void kernel_launch(void* const* d_in, const int* in_sizes, int n_in,
                              void* d_out, int out_size)
{
    (void)in_sizes; (void)n_in; (void)out_size;
    const float* x    = (const float*)d_in[0];
    const float* mask = (const float*)d_in[1];
    const float* Wih  = (const float*)d_in[2];
    const float* Whh  = (const float*)d_in[3];
    const float* bih  = (const float*)d_in[4];
    const float* bhh  = (const float*)d_in[5];
    float* out = (float*)d_out;

    cudaFuncSetAttribute(gru_rec_kernel,
                         cudaFuncAttributeMaxDynamicSharedMemorySize,
                         SMEM_B_BYTES);

    split_x_kernel<<<(Bsz * Ssz * Dsz) / (256 * 8), 256>>>(x);
    split_w_kernel<<<(Dsz * G3) / (256 * 8), 256>>>(Wih);

    dim3 gridA(G3 / 128, (Bsz * Ssz) / 128);
    gemm_gx_mma<<<gridA, 256, SMEM_GEMM>>>(bih);

    gru_rec_kernel<<<Bsz, TPB_B, SMEM_B_BYTES>>>(mask, Whh, bhh, out);
}